// round 1
// baseline (speedup 1.0000x reference)
#include <cuda_runtime.h>
#include <math.h>

// Problem constants (match reference)
#define Bb 16
#define Ss 128
#define Nn 64
#define Ee 128
#define Hh 128
#define Ll 32

// ---------------------------------------------------------------------------
// Scratch (device globals; no runtime allocation allowed)
// ---------------------------------------------------------------------------
__device__ float g_Xg[(size_t)2 * Bb * Ss * 4 * Hh];   // (dir,b,t,4H)  8 MB
__device__ float g_Xl[(size_t)2 * Bb * Ss * Hh];       // (dir,b,t,H)   2 MB
__device__ float g_Wg[(size_t)2 * Bb * Nn * 3 * Hh];   // (dir,b,n,3H)  3 MB
__device__ float g_feats[(size_t)Bb * Ss * 2 * Hh];    // (b,t,2H)      2 MB
__device__ float g_logits[(size_t)Bb * Ss * Ll];       // (b,t,L)
__device__ float g_pb[Bb];                             // per-batch loss

__device__ __forceinline__ float sigf(float x) { return 1.f / (1.f + expf(-x)); }

// ---------------------------------------------------------------------------
// Gather + GEMM:  out[b, t, :] = emb[ids[b, rev? L-1-t : t]] @ W + bias
// K = 128 fixed. Each block: 16 rows, 128 threads, NCOL/128 cols per thread.
// ---------------------------------------------------------------------------
template <int NCOL>
__global__ void gather_gemm_kernel(const float* __restrict__ emb,
                                   const int* __restrict__ ids,
                                   int Lrow, int rev,
                                   const float* __restrict__ W,
                                   const float* __restrict__ bias,
                                   float* __restrict__ out)
{
    constexpr int K   = 128;
    constexpr int RT  = 16;
    constexpr int CPT = NCOL / 128;

    __shared__ float xs[RT][K];

    int b   = blockIdx.x;
    int r0  = blockIdx.y * RT;
    int tid = threadIdx.x;

    for (int idx = tid; idx < RT * K; idx += 128) {
        int r = idx >> 7;
        int e = idx & 127;
        int t = r0 + r;
        int src = rev ? (Lrow - 1 - t) : t;
        int id = ids[b * Lrow + src];
        xs[r][e] = emb[(size_t)id * K + e];
    }
    __syncthreads();

    float acc[RT][CPT];
#pragma unroll
    for (int r = 0; r < RT; r++)
#pragma unroll
        for (int c = 0; c < CPT; c++) acc[r][c] = 0.f;

    for (int e = 0; e < K; e++) {
        float w[CPT];
#pragma unroll
        for (int c = 0; c < CPT; c++) w[c] = W[e * NCOL + tid + c * 128];
#pragma unroll
        for (int r = 0; r < RT; r++) {
            float x = xs[r][e];
#pragma unroll
            for (int c = 0; c < CPT; c++) acc[r][c] = fmaf(x, w[c], acc[r][c]);
        }
    }

#pragma unroll
    for (int r = 0; r < RT; r++)
#pragma unroll
        for (int c = 0; c < CPT; c++)
            out[((size_t)b * Lrow + r0 + r) * NCOL + tid + c * 128] =
                acc[r][c] + bias[tid + c * 128];
}

// ---------------------------------------------------------------------------
// Lattice LSTM recurrence. One CTA per (dir, batch). 512 threads.
// h_hist / c_hist live in dynamic shared memory.
// ---------------------------------------------------------------------------
constexpr int SMEM_LAT =
    (2 * (Ss + 1) * Hh   // h_hist, c_hist
     + 4 * Hh            // gates
     + 3 * Hh            // wtmp
     + Hh                // cw
     + Hh                // sum_ew
     + Hh) * 4           // sum_ewcw
    + (3 * Nn + 1) * 4;  // w_end, w_beg, widx, mcnt

__global__ void lattice_kernel(const float* __restrict__ Wch_f, const float* __restrict__ Wch_r,
                               const float* __restrict__ Wwh_f, const float* __restrict__ Wwh_r,
                               const float* __restrict__ Wlc_f, const float* __restrict__ Wlc_r,
                               const int* __restrict__ word_begin,
                               const int* __restrict__ word_len,
                               const int* __restrict__ seqlen)
{
    extern __shared__ float sm[];
    float* h_hist   = sm;                           // (S+1)*H
    float* c_hist   = h_hist + (Ss + 1) * Hh;       // (S+1)*H
    float* gates    = c_hist + (Ss + 1) * Hh;       // 4H
    float* wtmp     = gates + 4 * Hh;               // 3H
    float* cw       = wtmp + 3 * Hh;                // H
    float* sum_ew   = cw + Hh;                      // H
    float* sum_ewcw = sum_ew + Hh;                  // H
    int*   w_end    = (int*)(sum_ewcw + Hh);        // N
    int*   w_beg    = w_end + Nn;                   // N
    int*   widx     = w_beg + Nn;                   // N
    int*   mcnt     = widx + Nn;                    // 1

    int dirb = blockIdx.x;          // dir*B + b
    int dir  = dirb / Bb;
    int b    = dirb - dir * Bb;
    int tid  = threadIdx.x;
    int sl   = seqlen[b];

    const float* Wch = dir ? Wch_r : Wch_f;
    const float* Wwh = dir ? Wwh_r : Wwh_f;
    const float* Wlc = dir ? Wlc_r : Wlc_f;

    const float* Xg_b = g_Xg + (size_t)dirb * Ss * (4 * Hh);
    const float* Xl_b = g_Xl + (size_t)dirb * Ss * Hh;
    const float* Wg_b = g_Wg + (size_t)dirb * Nn * (3 * Hh);

    // init: zero state row 0
    if (tid < Hh) { h_hist[tid] = 0.f; c_hist[tid] = 0.f; }

    // per-word (begin,end) in this direction's coordinates; invalid -> end=-1
    if (tid < Nn) {
        int bg = word_begin[b * Nn + tid];
        int ln = word_len[b * Nn + tid];
        int ef = min(bg + ln, Ss - 1);
        bool valid = ef < sl;
        if (dir == 0) {
            w_beg[tid] = bg;
            w_end[tid] = valid ? ef : -1;
        } else {
            w_beg[tid] = Ss - 1 - ef;
            w_end[tid] = valid ? (Ss - 1 - bg) : -1;
        }
    }
    __syncthreads();

    for (int t = 0; t < Ss; t++) {
        // ---- char gates: gates[k] = Xg[t,k] + sum_j h_prev[j] * Wch[j,k] ----
        {
            const float* xg = Xg_b + (size_t)t * (4 * Hh);
            const float* hp = h_hist + t * Hh;
            float acc = xg[tid];
            const float* wcol = Wch + tid;
#pragma unroll 8
            for (int j = 0; j < Hh; j++) acc = fmaf(hp[j], wcol[j * (4 * Hh)], acc);
            gates[tid] = acc;
        }
        // ---- deterministic gather of words ending at t ----
        if (tid == 0) {
            int c = 0;
            for (int n = 0; n < Nn; n++)
                if (w_end[n] == t) widx[c++] = n;
            *mcnt = c;
        }
        __syncthreads();
        int m = *mcnt;

        if (m > 0) {
            if (tid < Hh) { sum_ew[tid] = 0.f; sum_ewcw[tid] = 0.f; }
            __syncthreads();
            for (int wv = 0; wv < m; wv++) {
                int n  = widx[wv];
                int bg = w_beg[n];
                const float* hb = h_hist + bg * Hh;
                const float* cb = c_hist + bg * Hh;
                if (tid < 3 * Hh) {
                    float acc = Wg_b[(size_t)n * (3 * Hh) + tid];
                    const float* wcol = Wwh + tid;
#pragma unroll 8
                    for (int j = 0; j < Hh; j++) acc = fmaf(hb[j], wcol[j * (3 * Hh)], acc);
                    wtmp[tid] = acc;
                }
                __syncthreads();
                if (tid < Hh) {
                    float wig = sigf(wtmp[tid]);
                    float wfg = sigf(wtmp[Hh + tid]);
                    float wgg = tanhf(wtmp[2 * Hh + tid]);
                    cw[tid] = wfg * cb[tid] + wig * wgg;
                }
                __syncthreads();
                if (tid < Hh) {
                    float acc = Xl_b[(size_t)t * Hh + tid];
                    const float* wcol = Wlc + tid;
#pragma unroll 8
                    for (int j = 0; j < Hh; j++) acc = fmaf(cw[j], wcol[j * Hh], acc);
                    float ew = expf(sigf(acc));
                    sum_ew[tid]   += ew;
                    sum_ewcw[tid] += ew * cw[tid];
                }
                __syncthreads();
            }
        } else {
            __syncthreads();
        }

        // ---- cell/state update ----
        if (tid < Hh) {
            float ig = sigf(gates[tid]);
            float fg = sigf(gates[Hh + tid]);
            float og = sigf(gates[2 * Hh + tid]);
            float gg = tanhf(gates[3 * Hh + tid]);
            float cp = c_hist[t * Hh + tid];
            float hpv = h_hist[t * Hh + tid];
            float ct;
            if (m > 0) {
                float ec = expf(ig);
                ct = (ec * gg + sum_ewcw[tid]) / (ec + sum_ew[tid]);
            } else {
                ct = fg * cp + ig * gg;
            }
            float ht = og * tanhf(ct);
            bool v = (dir == 0) ? (t < sl) : (t >= Ss - sl);
            h_hist[(t + 1) * Hh + tid] = v ? ht : hpv;
            c_hist[(t + 1) * Hh + tid] = v ? ct : cp;
            int tt = (dir == 0) ? t : (Ss - 1 - t);
            g_feats[((size_t)b * Ss + tt) * (2 * Hh) + dir * Hh + tid] = v ? ht : 0.f;
        }
        __syncthreads();
    }
}

// ---------------------------------------------------------------------------
// Dense projection: logits = feats @ dense_W + dense_b
// block = 256 threads, 8 (b,t) rows per block, 32 cols each.
// ---------------------------------------------------------------------------
__global__ void dense_kernel(const float* __restrict__ W, const float* __restrict__ bias)
{
    __shared__ float fs[8][2 * Hh];
    int row0 = blockIdx.x * 8;
    int tid = threadIdx.x;
    for (int idx = tid; idx < 8 * 2 * Hh; idx += 256) {
        int r = idx >> 8;
        int e = idx & 255;
        fs[r][e] = g_feats[(size_t)(row0 + r) * (2 * Hh) + e];
    }
    __syncthreads();
    int r = tid >> 5;
    int col = tid & 31;
    float acc = bias[col];
#pragma unroll 8
    for (int e = 0; e < 2 * Hh; e++) acc = fmaf(fs[r][e], W[e * Ll + col], acc);
    g_logits[(size_t)(row0 + r) * Ll + col] = acc;
}

// ---------------------------------------------------------------------------
// CRF: gold score + forward algorithm per batch; one warp per batch.
// ---------------------------------------------------------------------------
__global__ void crf_kernel(const int* __restrict__ label,
                           const int* __restrict__ seqlen,
                           const float* __restrict__ T)
{
    int b = blockIdx.x;
    int j = threadIdx.x;   // label column 0..31
    int sl = seqlen[b];
    const float* lg = g_logits + (size_t)b * Ss * Ll;
    const int*   lab = label + b * Ss;

    float Tc[32];
#pragma unroll
    for (int i = 0; i < 32; i++) Tc[i] = T[i * Ll + j];

    // gold = sum emit*mask + sum trans*mask[1:]
    float gold = 0.f;
    for (int t = j; t < Ss; t += 32)
        if (t < sl) gold += lg[t * Ll + lab[t]];
    for (int t = j + 1; t < Ss; t += 32)
        if (t < sl) gold += T[lab[t - 1] * Ll + lab[t]];
#pragma unroll
    for (int o = 16; o; o >>= 1) gold += __shfl_xor_sync(0xffffffffu, gold, o);

    // forward algorithm
    float alpha = lg[j];
    for (int t = 1; t < Ss; t++) {
        float vmax = -1e30f;
#pragma unroll
        for (int i = 0; i < 32; i++) {
            float ai = __shfl_sync(0xffffffffu, alpha, i);
            vmax = fmaxf(vmax, ai + Tc[i]);
        }
        float s = 0.f;
#pragma unroll
        for (int i = 0; i < 32; i++) {
            float ai = __shfl_sync(0xffffffffu, alpha, i);
            s += expf(ai + Tc[i] - vmax);
        }
        float na = vmax + logf(s) + lg[(size_t)t * Ll + j];
        if (t < sl) alpha = na;
    }
    // logZ = logsumexp(alpha)
    float m2 = alpha;
#pragma unroll
    for (int o = 16; o; o >>= 1) m2 = fmaxf(m2, __shfl_xor_sync(0xffffffffu, m2, o));
    float s2 = expf(alpha - m2);
#pragma unroll
    for (int o = 16; o; o >>= 1) s2 += __shfl_xor_sync(0xffffffffu, s2, o);
    if (j == 0) g_pb[b] = (m2 + logf(s2)) - gold;
}

__global__ void finalize_kernel(float* __restrict__ out)
{
    float s = 0.f;
#pragma unroll
    for (int i = 0; i < Bb; i++) s += g_pb[i];
    out[0] = s / (float)Bb;
}

// ---------------------------------------------------------------------------
// Launch
// ---------------------------------------------------------------------------
extern "C" void kernel_launch(void* const* d_in, const int* in_sizes, int n_in,
                              void* d_out, int out_size)
{
    const int* char_ids = (const int*)d_in[0];
    const int* kb_ids   = (const int*)d_in[1];
    const int* wbeg     = (const int*)d_in[2];
    const int* wlen     = (const int*)d_in[3];
    const int* label    = (const int*)d_in[4];
    const int* slen     = (const int*)d_in[5];
    const float* char_emb = (const float*)d_in[6];
    const float* kb_emb   = (const float*)d_in[7];
    const float* dense_W  = (const float*)d_in[8];
    const float* dense_b  = (const float*)d_in[9];
    const float* crf_T    = (const float*)d_in[10];

    const float* f_Wcx = (const float*)d_in[11];
    const float* f_Wch = (const float*)d_in[12];
    const float* f_bc  = (const float*)d_in[13];
    const float* f_Wwx = (const float*)d_in[14];
    const float* f_Wwh = (const float*)d_in[15];
    const float* f_bw  = (const float*)d_in[16];
    const float* f_Wlx = (const float*)d_in[17];
    const float* f_Wlc = (const float*)d_in[18];
    const float* f_bl  = (const float*)d_in[19];

    const float* r_Wcx = (const float*)d_in[20];
    const float* r_Wch = (const float*)d_in[21];
    const float* r_bc  = (const float*)d_in[22];
    const float* r_Wwx = (const float*)d_in[23];
    const float* r_Wwh = (const float*)d_in[24];
    const float* r_bw  = (const float*)d_in[25];
    const float* r_Wlx = (const float*)d_in[26];
    const float* r_Wlc = (const float*)d_in[27];
    const float* r_bl  = (const float*)d_in[28];

    float *pXg, *pXl, *pWg;
    cudaGetSymbolAddress((void**)&pXg, g_Xg);
    cudaGetSymbolAddress((void**)&pXl, g_Xl);
    cudaGetSymbolAddress((void**)&pWg, g_Wg);

    // Phase 1: gather-GEMM precomputes
    dim3 gx(Bb, Ss / 16);
    gather_gemm_kernel<512><<<gx, 128>>>(char_emb, char_ids, Ss, 0, f_Wcx, f_bc, pXg);
    gather_gemm_kernel<512><<<gx, 128>>>(char_emb, char_ids, Ss, 1, r_Wcx, r_bc,
                                         pXg + (size_t)Bb * Ss * 512);
    gather_gemm_kernel<128><<<gx, 128>>>(char_emb, char_ids, Ss, 0, f_Wlx, f_bl, pXl);
    gather_gemm_kernel<128><<<gx, 128>>>(char_emb, char_ids, Ss, 1, r_Wlx, r_bl,
                                         pXl + (size_t)Bb * Ss * 128);
    dim3 gw(Bb, Nn / 16);
    gather_gemm_kernel<384><<<gw, 128>>>(kb_emb, kb_ids, Nn, 0, f_Wwx, f_bw, pWg);
    gather_gemm_kernel<384><<<gw, 128>>>(kb_emb, kb_ids, Nn, 1, r_Wwx, r_bw,
                                         pWg + (size_t)Bb * Nn * 384);

    // Phase 2: recurrent lattice (32 CTAs, 512 threads, 138KB smem each)
    cudaFuncSetAttribute(lattice_kernel, cudaFuncAttributeMaxDynamicSharedMemorySize, SMEM_LAT);
    lattice_kernel<<<2 * Bb, 512, SMEM_LAT>>>(f_Wch, r_Wch, f_Wwh, r_Wwh, f_Wlc, r_Wlc,
                                              wbeg, wlen, slen);

    // Phase 3: dense + CRF + reduce
    dense_kernel<<<(Bb * Ss) / 8, 256>>>(dense_W, dense_b);
    crf_kernel<<<Bb, 32>>>(label, slen, crf_T);
    finalize_kernel<<<1, 1>>>((float*)d_out);
}

// round 2
// speedup vs baseline: 1.4035x; 1.4035x over previous
#include <cuda_runtime.h>
#include <math.h>

#define Bb 16
#define Ss 128
#define Nn 64
#define Ee 128
#define Hh 128
#define Ll 32

// ---------------------------------------------------------------------------
// Device-global scratch (no runtime allocation allowed)
// ---------------------------------------------------------------------------
__device__ float g_Xg[(size_t)2 * Bb * Ss * 4 * Hh];   // (dir,b,t,512)
__device__ float g_Xl[(size_t)2 * Bb * Ss * Hh];       // (dir,b,t,128)
__device__ float g_Wg[(size_t)2 * Bb * Nn * 3 * Hh];   // (dir,b,n,384)
__device__ float g_WwhT[(size_t)2 * 3 * Hh * Hh];      // (dir,k(384),j(128)) transposed
__device__ float g_WlcT[(size_t)2 * Hh * Hh];          // (dir,k(128),j(128)) transposed
__device__ float g_feats[(size_t)Bb * Ss * 2 * Hh];    // (b,t,256)
__device__ float g_logits[(size_t)Bb * Ss * Ll];
__device__ float g_pb[Bb];

__device__ __forceinline__ float sigf(float x) { return 1.f / (1.f + expf(-x)); }

// ---------------------------------------------------------------------------
// Prep: transpose Wwh (128x384 -> 384x128) and Wlc (128x128 -> T), both dirs
// ---------------------------------------------------------------------------
__global__ void prep_transpose_kernel(const float* __restrict__ fWwh,
                                      const float* __restrict__ rWwh,
                                      const float* __restrict__ fWlc,
                                      const float* __restrict__ rWlc)
{
    int which = blockIdx.y;
    const float* in;
    float* out;
    int K;
    if (which == 0)      { in = fWwh; out = g_WwhT;               K = 384; }
    else if (which == 1) { in = rWwh; out = g_WwhT + 384 * 128;   K = 384; }
    else if (which == 2) { in = fWlc; out = g_WlcT;               K = 128; }
    else                 { in = rWlc; out = g_WlcT + 128 * 128;   K = 128; }
    int idx = blockIdx.x * 256 + threadIdx.x;
    if (idx < K * 128) {
        int k = idx >> 7;
        int j = idx & 127;
        out[idx] = in[j * K + k];   // out[k*128+j]
    }
}

// ---------------------------------------------------------------------------
// Fused char-side gather GEMM: X(16x8 rows tile) x [f_Wcx|r_Wcx|f_Wlx|r_Wlx]
// 1280 output columns. 256 threads, 5 columns each, 8 rows per CTA.
// Reverse-direction outputs are written at reversed row index.
// ---------------------------------------------------------------------------
__global__ void __launch_bounds__(256) char_gather_kernel(
    const float* __restrict__ emb, const int* __restrict__ ids,
    const float* __restrict__ fWcx, const float* __restrict__ rWcx,
    const float* __restrict__ fWlx, const float* __restrict__ rWlx,
    const float* __restrict__ fbc, const float* __restrict__ rbc,
    const float* __restrict__ fbl, const float* __restrict__ rbl)
{
    __shared__ float xs[8][128];
    int b = blockIdx.x, r0 = blockIdx.y * 8, tid = threadIdx.x;

    for (int idx = tid; idx < 8 * 128; idx += 256) {
        int r = idx >> 7, e = idx & 127;
        int id = ids[b * Ss + r0 + r];
        xs[r][e] = emb[(size_t)id * 128 + e];
    }
    __syncthreads();

    const float* wp[5];
    float bias[5];
    float* op[5];
    int ostep[5];

    // s=0,1: forward Wcx (cols tid, tid+256)
    wp[0] = fWcx + tid;        bias[0] = fbc[tid];
    wp[1] = fWcx + tid + 256;  bias[1] = fbc[tid + 256];
    op[0] = g_Xg + ((size_t)b * Ss + r0) * 512 + tid;
    op[1] = op[0] + 256;
    ostep[0] = ostep[1] = 512;
    // s=2,3: reverse Wcx, reversed rows
    wp[2] = rWcx + tid;        bias[2] = rbc[tid];
    wp[3] = rWcx + tid + 256;  bias[3] = rbc[tid + 256];
    op[2] = g_Xg + ((size_t)(Bb + b) * Ss + (Ss - 1 - r0)) * 512 + tid;
    op[3] = op[2] + 256;
    ostep[2] = ostep[3] = -512;
    // s=4: Wlx (128 cols each dir)
    if (tid < 128) {
        wp[4] = fWlx + tid; bias[4] = fbl[tid];
        op[4] = g_Xl + ((size_t)b * Ss + r0) * 128 + tid;
        ostep[4] = 128;
    } else {
        int c = tid - 128;
        wp[4] = rWlx + c; bias[4] = rbl[c];
        op[4] = g_Xl + ((size_t)(Bb + b) * Ss + (Ss - 1 - r0)) * 128 + c;
        ostep[4] = -128;
    }

    float acc[8][5];
#pragma unroll
    for (int r = 0; r < 8; r++)
#pragma unroll
        for (int s = 0; s < 5; s++) acc[r][s] = 0.f;

    for (int e = 0; e < 128; e++) {
        float w0 = wp[0][(size_t)e * 512];
        float w1 = wp[1][(size_t)e * 512];
        float w2 = wp[2][(size_t)e * 512];
        float w3 = wp[3][(size_t)e * 512];
        float w4 = wp[4][(size_t)e * 128];
#pragma unroll
        for (int r = 0; r < 8; r++) {
            float x = xs[r][e];
            acc[r][0] = fmaf(x, w0, acc[r][0]);
            acc[r][1] = fmaf(x, w1, acc[r][1]);
            acc[r][2] = fmaf(x, w2, acc[r][2]);
            acc[r][3] = fmaf(x, w3, acc[r][3]);
            acc[r][4] = fmaf(x, w4, acc[r][4]);
        }
    }

#pragma unroll
    for (int r = 0; r < 8; r++)
#pragma unroll
        for (int s = 0; s < 5; s++)
            op[s][(long)r * ostep[s]] = acc[r][s] + bias[s];
}

// ---------------------------------------------------------------------------
// Fused kb-side gather GEMM: Xw(8 rows) x [f_Wwx|r_Wwx], 768 cols.
// ---------------------------------------------------------------------------
__global__ void __launch_bounds__(256) kb_gather_kernel(
    const float* __restrict__ emb, const int* __restrict__ ids,
    const float* __restrict__ fW, const float* __restrict__ rW,
    const float* __restrict__ fb, const float* __restrict__ rb)
{
    __shared__ float xs[8][128];
    int b = blockIdx.x, r0 = blockIdx.y * 8, tid = threadIdx.x;

    for (int idx = tid; idx < 8 * 128; idx += 256) {
        int r = idx >> 7, e = idx & 127;
        int id = ids[b * Nn + r0 + r];
        xs[r][e] = emb[(size_t)id * 128 + e];
    }
    __syncthreads();

    const float* wp[3];
    float bias[3];
    float* op[3];
#pragma unroll
    for (int s = 0; s < 3; s++) {
        int c = tid + 256 * s;
        if (c < 384) {
            wp[s] = fW + c; bias[s] = fb[c];
            op[s] = g_Wg + ((size_t)b * Nn + r0) * 384 + c;
        } else {
            int c2 = c - 384;
            wp[s] = rW + c2; bias[s] = rb[c2];
            op[s] = g_Wg + ((size_t)(Bb + b) * Nn + r0) * 384 + c2;
        }
    }

    float acc[8][3];
#pragma unroll
    for (int r = 0; r < 8; r++)
#pragma unroll
        for (int s = 0; s < 3; s++) acc[r][s] = 0.f;

    for (int e = 0; e < 128; e++) {
        float w0 = wp[0][(size_t)e * 384];
        float w1 = wp[1][(size_t)e * 384];
        float w2 = wp[2][(size_t)e * 384];
#pragma unroll
        for (int r = 0; r < 8; r++) {
            float x = xs[r][e];
            acc[r][0] = fmaf(x, w0, acc[r][0]);
            acc[r][1] = fmaf(x, w1, acc[r][1]);
            acc[r][2] = fmaf(x, w2, acc[r][2]);
        }
    }

#pragma unroll
    for (int r = 0; r < 8; r++)
#pragma unroll
        for (int s = 0; s < 3; s++)
            op[s][(size_t)r * 384] = acc[r][s] + bias[s];
}

// ---------------------------------------------------------------------------
// Lattice LSTM recurrence. One CTA per (dir,batch). 512 threads.
// Wch rows 0..87 in registers (88 regs/thread), rows 88..127 in smem.
// ---------------------------------------------------------------------------
#define RREG 88
#define RSM  40

// smem float offsets
#define OFF_H   0
#define OFF_C   16512
#define OFF_W   33024
#define OFF_G   53504
#define OFF_WT  54016
#define OFF_CW  54400
#define OFF_SE  54528
#define OFF_SC  54656
#define OFF_PS  54784
#define FLT_END 55296
// ints after floats: w_beg[64], w_end[64], wl_start[129], wl_idx[64], cur[128]
#define INT_CNT 449
#define SMEM_LAT (FLT_END * 4 + INT_CNT * 4)

__global__ void __launch_bounds__(512, 1) lattice_kernel(
    const float* __restrict__ Wch_f, const float* __restrict__ Wch_r,
    const int* __restrict__ word_begin, const int* __restrict__ word_len,
    const int* __restrict__ seqlen)
{
    extern __shared__ float sm[];
    float* h_hist   = sm + OFF_H;
    float* c_hist   = sm + OFF_C;
    float* wsm      = sm + OFF_W;
    float* gates    = sm + OFF_G;
    float* wtmp     = sm + OFF_WT;
    float* cw       = sm + OFF_CW;
    float* sum_ew   = sm + OFF_SE;
    float* sum_ewcw = sm + OFF_SC;
    float* psum     = sm + OFF_PS;
    int* ip        = (int*)(sm + FLT_END);
    int* w_beg     = ip;
    int* w_end     = ip + 64;
    int* wl_start  = ip + 128;     // 129 entries
    int* wl_idx    = ip + 257;     // 64
    int* cur       = ip + 321;     // 128

    int dirb = blockIdx.x;
    int dir  = dirb / Bb;
    int b    = dirb - dir * Bb;
    int tid  = threadIdx.x;
    int sl   = seqlen[b];

    const float* Wch  = dir ? Wch_r : Wch_f;
    const float* WwhT = g_WwhT + (size_t)dir * 384 * 128;
    const float* WlcT = g_WlcT + (size_t)dir * 128 * 128;
    const float* Xg_b = g_Xg + (size_t)dirb * Ss * 512;
    const float* Xl_b = g_Xl + (size_t)dirb * Ss * 128;
    const float* Wg_b = g_Wg + (size_t)dirb * Nn * 384;

    // load register-resident weight rows (column tid)
    float wreg[RREG];
#pragma unroll
    for (int r = 0; r < RREG; r++) wreg[r] = Wch[(size_t)r * 512 + tid];
    // smem weight rows
#pragma unroll
    for (int r = 0; r < RSM; r++) wsm[r * 512 + tid] = Wch[(size_t)(RREG + r) * 512 + tid];

    if (tid < Hh) { h_hist[tid] = 0.f; c_hist[tid] = 0.f; }

    // per-word begin/end in this direction's coordinates
    if (tid < Nn) {
        int bg = word_begin[b * Nn + tid];
        int ln = word_len[b * Nn + tid];
        int ef = min(bg + ln, Ss - 1);
        bool valid = ef < sl;
        if (dir == 0) {
            w_beg[tid] = bg;
            w_end[tid] = valid ? ef : -1;
        } else {
            w_beg[tid] = Ss - 1 - ef;
            w_end[tid] = valid ? (Ss - 1 - bg) : -1;
        }
    }
    __syncthreads();

    // build per-step word lists (counting sort), single thread, once
    if (tid == 0) {
        for (int t = 0; t < Ss; t++) cur[t] = 0;
        for (int n = 0; n < Nn; n++) { int e = w_end[n]; if (e >= 0) cur[e]++; }
        wl_start[0] = 0;
        for (int t = 0; t < Ss; t++) wl_start[t + 1] = wl_start[t] + cur[t];
        for (int t = 0; t < Ss; t++) cur[t] = wl_start[t];
        for (int n = 0; n < Nn; n++) { int e = w_end[n]; if (e >= 0) wl_idx[cur[e]++] = n; }
    }
    __syncthreads();

    for (int t = 0; t < Ss; t++) {
        int wls = wl_start[t];
        int m = wl_start[t + 1] - wls;

        // ---- char gates matvec: reg + smem weights, h via float4 ----
        {
            const float4* h4 = (const float4*)(h_hist + t * Hh);
            float a0 = Xg_b[(size_t)t * 512 + tid];
            float a1 = 0.f;
#pragma unroll
            for (int r = 0; r < 22; r += 2) {
                float4 hv0 = h4[r], hv1 = h4[r + 1];
                a0 = fmaf(hv0.x, wreg[4 * r + 0], a0);
                a0 = fmaf(hv0.y, wreg[4 * r + 1], a0);
                a0 = fmaf(hv0.z, wreg[4 * r + 2], a0);
                a0 = fmaf(hv0.w, wreg[4 * r + 3], a0);
                a1 = fmaf(hv1.x, wreg[4 * r + 4], a1);
                a1 = fmaf(hv1.y, wreg[4 * r + 5], a1);
                a1 = fmaf(hv1.z, wreg[4 * r + 6], a1);
                a1 = fmaf(hv1.w, wreg[4 * r + 7], a1);
            }
#pragma unroll
            for (int r = 0; r < 10; r += 2) {
                float4 hv0 = h4[22 + r], hv1 = h4[23 + r];
                a0 = fmaf(hv0.x, wsm[(4 * r + 0) * 512 + tid], a0);
                a0 = fmaf(hv0.y, wsm[(4 * r + 1) * 512 + tid], a0);
                a0 = fmaf(hv0.z, wsm[(4 * r + 2) * 512 + tid], a0);
                a0 = fmaf(hv0.w, wsm[(4 * r + 3) * 512 + tid], a0);
                a1 = fmaf(hv1.x, wsm[(4 * r + 4) * 512 + tid], a1);
                a1 = fmaf(hv1.y, wsm[(4 * r + 5) * 512 + tid], a1);
                a1 = fmaf(hv1.z, wsm[(4 * r + 6) * 512 + tid], a1);
                a1 = fmaf(hv1.w, wsm[(4 * r + 7) * 512 + tid], a1);
            }
            gates[tid] = a0 + a1;
            if (m > 0 && tid < Hh) { sum_ew[tid] = 0.f; sum_ewcw[tid] = 0.f; }
        }
        __syncthreads();

        // ---- word lattice contributions ----
        for (int wv = 0; wv < m; wv++) {
            int n  = wl_idx[wls + wv];
            int bg = w_beg[n];
            if (tid < 384) {
                const float4* hb4 = (const float4*)(h_hist + bg * Hh);
                const float4* wT  = (const float4*)(WwhT + (size_t)tid * 128);
                float a0 = Wg_b[(size_t)n * 384 + tid], a1 = 0.f;
#pragma unroll
                for (int r = 0; r < 32; r += 2) {
                    float4 hv0 = hb4[r],  wv0 = wT[r];
                    float4 hv1 = hb4[r + 1], wv1 = wT[r + 1];
                    a0 = fmaf(hv0.x, wv0.x, a0);
                    a0 = fmaf(hv0.y, wv0.y, a0);
                    a0 = fmaf(hv0.z, wv0.z, a0);
                    a0 = fmaf(hv0.w, wv0.w, a0);
                    a1 = fmaf(hv1.x, wv1.x, a1);
                    a1 = fmaf(hv1.y, wv1.y, a1);
                    a1 = fmaf(hv1.z, wv1.z, a1);
                    a1 = fmaf(hv1.w, wv1.w, a1);
                }
                wtmp[tid] = a0 + a1;
            }
            __syncthreads();
            if (tid < Hh) {
                float wig = sigf(wtmp[tid]);
                float wfg = sigf(wtmp[Hh + tid]);
                float wgg = tanhf(wtmp[2 * Hh + tid]);
                cw[tid] = wfg * c_hist[bg * Hh + tid] + wig * wgg;
            }
            __syncthreads();
            // Wlc matvec split-K over 4 slices of 32 j's
            {
                int col = tid & 127, sl4 = tid >> 7;
                const float4* c4 = (const float4*)cw + sl4 * 8;
                const float4* wT = (const float4*)(WlcT + (size_t)col * 128) + sl4 * 8;
                float p0 = 0.f, p1 = 0.f;
#pragma unroll
                for (int r = 0; r < 8; r += 2) {
                    float4 cv0 = c4[r],  wv0 = wT[r];
                    float4 cv1 = c4[r + 1], wv1 = wT[r + 1];
                    p0 = fmaf(cv0.x, wv0.x, p0);
                    p0 = fmaf(cv0.y, wv0.y, p0);
                    p0 = fmaf(cv0.z, wv0.z, p0);
                    p0 = fmaf(cv0.w, wv0.w, p0);
                    p1 = fmaf(cv1.x, wv1.x, p1);
                    p1 = fmaf(cv1.y, wv1.y, p1);
                    p1 = fmaf(cv1.z, wv1.z, p1);
                    p1 = fmaf(cv1.w, wv1.w, p1);
                }
                psum[sl4 * 128 + col] = p0 + p1;
            }
            __syncthreads();
            if (tid < Hh) {
                float a = Xl_b[(size_t)t * 128 + tid]
                        + psum[tid] + psum[128 + tid] + psum[256 + tid] + psum[384 + tid];
                float ew = expf(sigf(a));
                sum_ew[tid]   += ew;
                sum_ewcw[tid] += ew * cw[tid];
            }
            __syncthreads();
        }

        // ---- cell/state update ----
        if (tid < Hh) {
            float ig = sigf(gates[tid]);
            float fg = sigf(gates[Hh + tid]);
            float og = sigf(gates[2 * Hh + tid]);
            float gg = tanhf(gates[3 * Hh + tid]);
            float cp  = c_hist[t * Hh + tid];
            float hpv = h_hist[t * Hh + tid];
            float ct;
            if (m > 0) {
                float ec = expf(ig);
                ct = (ec * gg + sum_ewcw[tid]) / (ec + sum_ew[tid]);
            } else {
                ct = fg * cp + ig * gg;
            }
            float ht = og * tanhf(ct);
            bool v = (dir == 0) ? (t < sl) : (t >= Ss - sl);
            h_hist[(t + 1) * Hh + tid] = v ? ht : hpv;
            c_hist[(t + 1) * Hh + tid] = v ? ct : cp;
            int tt = (dir == 0) ? t : (Ss - 1 - t);
            g_feats[((size_t)b * Ss + tt) * (2 * Hh) + dir * Hh + tid] = v ? ht : 0.f;
        }
        __syncthreads();
    }
}

// ---------------------------------------------------------------------------
// Dense projection: logits = feats @ dense_W + dense_b
// ---------------------------------------------------------------------------
__global__ void dense_kernel(const float* __restrict__ W, const float* __restrict__ bias)
{
    __shared__ float fs[8][2 * Hh];
    int row0 = blockIdx.x * 8;
    int tid = threadIdx.x;
    for (int idx = tid; idx < 8 * 2 * Hh; idx += 256) {
        int r = idx >> 8;
        int e = idx & 255;
        fs[r][e] = g_feats[(size_t)(row0 + r) * (2 * Hh) + e];
    }
    __syncthreads();
    int r = tid >> 5;
    int col = tid & 31;
    float acc = bias[col];
#pragma unroll 8
    for (int e = 0; e < 2 * Hh; e++) acc = fmaf(fs[r][e], W[e * Ll + col], acc);
    g_logits[(size_t)(row0 + r) * Ll + col] = acc;
}

// ---------------------------------------------------------------------------
// CRF: gold score + forward algorithm per batch; one warp per batch.
// ---------------------------------------------------------------------------
__global__ void crf_kernel(const int* __restrict__ label,
                           const int* __restrict__ seqlen,
                           const float* __restrict__ T)
{
    int b = blockIdx.x;
    int j = threadIdx.x;
    int sl = seqlen[b];
    const float* lg = g_logits + (size_t)b * Ss * Ll;
    const int*   lab = label + b * Ss;

    float Tc[32];
#pragma unroll
    for (int i = 0; i < 32; i++) Tc[i] = T[i * Ll + j];

    float gold = 0.f;
    for (int t = j; t < Ss; t += 32)
        if (t < sl) gold += lg[t * Ll + lab[t]];
    for (int t = j + 1; t < Ss; t += 32)
        if (t < sl) gold += T[lab[t - 1] * Ll + lab[t]];
#pragma unroll
    for (int o = 16; o; o >>= 1) gold += __shfl_xor_sync(0xffffffffu, gold, o);

    float alpha = lg[j];
    for (int t = 1; t < Ss; t++) {
        float vmax = -1e30f;
#pragma unroll
        for (int i = 0; i < 32; i++) {
            float ai = __shfl_sync(0xffffffffu, alpha, i);
            vmax = fmaxf(vmax, ai + Tc[i]);
        }
        float s = 0.f;
#pragma unroll
        for (int i = 0; i < 32; i++) {
            float ai = __shfl_sync(0xffffffffu, alpha, i);
            s += expf(ai + Tc[i] - vmax);
        }
        float na = vmax + logf(s) + lg[(size_t)t * Ll + j];
        if (t < sl) alpha = na;
    }
    float m2 = alpha;
#pragma unroll
    for (int o = 16; o; o >>= 1) m2 = fmaxf(m2, __shfl_xor_sync(0xffffffffu, m2, o));
    float s2 = expf(alpha - m2);
#pragma unroll
    for (int o = 16; o; o >>= 1) s2 += __shfl_xor_sync(0xffffffffu, s2, o);
    if (j == 0) g_pb[b] = (m2 + logf(s2)) - gold;
}

__global__ void finalize_kernel(float* __restrict__ out)
{
    float s = 0.f;
#pragma unroll
    for (int i = 0; i < Bb; i++) s += g_pb[i];
    out[0] = s / (float)Bb;
}

// ---------------------------------------------------------------------------
// Launch
// ---------------------------------------------------------------------------
extern "C" void kernel_launch(void* const* d_in, const int* in_sizes, int n_in,
                              void* d_out, int out_size)
{
    const int* char_ids = (const int*)d_in[0];
    const int* kb_ids   = (const int*)d_in[1];
    const int* wbeg     = (const int*)d_in[2];
    const int* wlen     = (const int*)d_in[3];
    const int* label    = (const int*)d_in[4];
    const int* slen     = (const int*)d_in[5];
    const float* char_emb = (const float*)d_in[6];
    const float* kb_emb   = (const float*)d_in[7];
    const float* dense_W  = (const float*)d_in[8];
    const float* dense_b  = (const float*)d_in[9];
    const float* crf_T    = (const float*)d_in[10];

    const float* f_Wcx = (const float*)d_in[11];
    const float* f_Wch = (const float*)d_in[12];
    const float* f_bc  = (const float*)d_in[13];
    const float* f_Wwx = (const float*)d_in[14];
    const float* f_Wwh = (const float*)d_in[15];
    const float* f_bw  = (const float*)d_in[16];
    const float* f_Wlx = (const float*)d_in[17];
    const float* f_Wlc = (const float*)d_in[18];
    const float* f_bl  = (const float*)d_in[19];

    const float* r_Wcx = (const float*)d_in[20];
    const float* r_Wch = (const float*)d_in[21];
    const float* r_bc  = (const float*)d_in[22];
    const float* r_Wwx = (const float*)d_in[23];
    const float* r_Wwh = (const float*)d_in[24];
    const float* r_bw  = (const float*)d_in[25];
    const float* r_Wlx = (const float*)d_in[26];
    const float* r_Wlc = (const float*)d_in[27];
    const float* r_bl  = (const float*)d_in[28];

    // Phase 0: transpose word weights (once per call, tiny)
    prep_transpose_kernel<<<dim3(192, 4), 256>>>(f_Wwh, r_Wwh, f_Wlc, r_Wlc);

    // Phase 1: fused gather-GEMMs
    char_gather_kernel<<<dim3(Bb, Ss / 8), 256>>>(char_emb, char_ids,
        f_Wcx, r_Wcx, f_Wlx, r_Wlx, f_bc, r_bc, f_bl, r_bl);
    kb_gather_kernel<<<dim3(Bb, Nn / 8), 256>>>(kb_emb, kb_ids,
        f_Wwx, r_Wwx, f_bw, r_bw);

    // Phase 2: recurrent lattice
    static int smem_set = 0;
    cudaFuncSetAttribute(lattice_kernel, cudaFuncAttributeMaxDynamicSharedMemorySize, SMEM_LAT);
    (void)smem_set;
    lattice_kernel<<<2 * Bb, 512, SMEM_LAT>>>(f_Wch, r_Wch, wbeg, wlen, slen);

    // Phase 3: dense + CRF + reduce
    dense_kernel<<<(Bb * Ss) / 8, 256>>>(dense_W, dense_b);
    crf_kernel<<<Bb, 32>>>(label, slen, crf_T);
    finalize_kernel<<<1, 1>>>((float*)d_out);
}

// round 3
// speedup vs baseline: 1.6387x; 1.1675x over previous
#include <cuda_runtime.h>
#include <math.h>

#define Bb 16
#define Ss 128
#define Nn 64
#define Ee 128
#define Hh 128
#define Ll 32

// ---------------------------------------------------------------------------
// Device-global scratch (no runtime allocation allowed)
// ---------------------------------------------------------------------------
__device__ float g_Xg[(size_t)2 * Bb * Ss * 4 * Hh];   // (dir,b,t,512)
__device__ float g_Xl[(size_t)2 * Bb * Ss * Hh];       // (dir,b,t,128)
__device__ float g_Wg[(size_t)2 * Bb * Nn * 3 * Hh];   // (dir,b,n,384)
__device__ float g_WwhT[(size_t)2 * 3 * Hh * Hh];      // (dir,k(384),j(128)) transposed
__device__ float g_WlcT[(size_t)2 * Hh * Hh];          // (dir,k(128),j(128)) transposed
__device__ float g_feats[(size_t)Bb * Ss * 2 * Hh];    // (b,t,256)
__device__ float g_logits[(size_t)Bb * Ss * Ll];
__device__ float g_pb[Bb];

__device__ __forceinline__ float sigf(float x) { return 1.f / (1.f + expf(-x)); }

// ---------------------------------------------------------------------------
// Prep: transpose Wwh (128x384 -> 384x128) and Wlc (128x128 -> T), both dirs
// ---------------------------------------------------------------------------
__global__ void prep_transpose_kernel(const float* __restrict__ fWwh,
                                      const float* __restrict__ rWwh,
                                      const float* __restrict__ fWlc,
                                      const float* __restrict__ rWlc)
{
    int which = blockIdx.y;
    const float* in;
    float* out;
    int K;
    if (which == 0)      { in = fWwh; out = g_WwhT;               K = 384; }
    else if (which == 1) { in = rWwh; out = g_WwhT + 384 * 128;   K = 384; }
    else if (which == 2) { in = fWlc; out = g_WlcT;               K = 128; }
    else                 { in = rWlc; out = g_WlcT + 128 * 128;   K = 128; }
    int idx = blockIdx.x * 256 + threadIdx.x;
    if (idx < K * 128) {
        int k = idx >> 7;
        int j = idx & 127;
        out[idx] = in[j * K + k];   // out[k*128+j]
    }
}

// ---------------------------------------------------------------------------
// Fused char-side gather GEMM (unchanged from R2: correct & cheap)
// ---------------------------------------------------------------------------
__global__ void __launch_bounds__(256) char_gather_kernel(
    const float* __restrict__ emb, const int* __restrict__ ids,
    const float* __restrict__ fWcx, const float* __restrict__ rWcx,
    const float* __restrict__ fWlx, const float* __restrict__ rWlx,
    const float* __restrict__ fbc, const float* __restrict__ rbc,
    const float* __restrict__ fbl, const float* __restrict__ rbl)
{
    __shared__ float xs[8][128];
    int b = blockIdx.x, r0 = blockIdx.y * 8, tid = threadIdx.x;

    for (int idx = tid; idx < 8 * 128; idx += 256) {
        int r = idx >> 7, e = idx & 127;
        int id = ids[b * Ss + r0 + r];
        xs[r][e] = emb[(size_t)id * 128 + e];
    }
    __syncthreads();

    const float* wp[5];
    float bias[5];
    float* op[5];
    int ostep[5];

    wp[0] = fWcx + tid;        bias[0] = fbc[tid];
    wp[1] = fWcx + tid + 256;  bias[1] = fbc[tid + 256];
    op[0] = g_Xg + ((size_t)b * Ss + r0) * 512 + tid;
    op[1] = op[0] + 256;
    ostep[0] = ostep[1] = 512;
    wp[2] = rWcx + tid;        bias[2] = rbc[tid];
    wp[3] = rWcx + tid + 256;  bias[3] = rbc[tid + 256];
    op[2] = g_Xg + ((size_t)(Bb + b) * Ss + (Ss - 1 - r0)) * 512 + tid;
    op[3] = op[2] + 256;
    ostep[2] = ostep[3] = -512;
    if (tid < 128) {
        wp[4] = fWlx + tid; bias[4] = fbl[tid];
        op[4] = g_Xl + ((size_t)b * Ss + r0) * 128 + tid;
        ostep[4] = 128;
    } else {
        int c = tid - 128;
        wp[4] = rWlx + c; bias[4] = rbl[c];
        op[4] = g_Xl + ((size_t)(Bb + b) * Ss + (Ss - 1 - r0)) * 128 + c;
        ostep[4] = -128;
    }

    float acc[8][5];
#pragma unroll
    for (int r = 0; r < 8; r++)
#pragma unroll
        for (int s = 0; s < 5; s++) acc[r][s] = 0.f;

    for (int e = 0; e < 128; e++) {
        float w0 = wp[0][(size_t)e * 512];
        float w1 = wp[1][(size_t)e * 512];
        float w2 = wp[2][(size_t)e * 512];
        float w3 = wp[3][(size_t)e * 512];
        float w4 = wp[4][(size_t)e * 128];
#pragma unroll
        for (int r = 0; r < 8; r++) {
            float x = xs[r][e];
            acc[r][0] = fmaf(x, w0, acc[r][0]);
            acc[r][1] = fmaf(x, w1, acc[r][1]);
            acc[r][2] = fmaf(x, w2, acc[r][2]);
            acc[r][3] = fmaf(x, w3, acc[r][3]);
            acc[r][4] = fmaf(x, w4, acc[r][4]);
        }
    }

#pragma unroll
    for (int r = 0; r < 8; r++)
#pragma unroll
        for (int s = 0; s < 5; s++)
            op[s][(long)r * ostep[s]] = acc[r][s] + bias[s];
}

// ---------------------------------------------------------------------------
// Fused kb-side gather GEMM (unchanged)
// ---------------------------------------------------------------------------
__global__ void __launch_bounds__(256) kb_gather_kernel(
    const float* __restrict__ emb, const int* __restrict__ ids,
    const float* __restrict__ fW, const float* __restrict__ rW,
    const float* __restrict__ fb, const float* __restrict__ rb)
{
    __shared__ float xs[8][128];
    int b = blockIdx.x, r0 = blockIdx.y * 8, tid = threadIdx.x;

    for (int idx = tid; idx < 8 * 128; idx += 256) {
        int r = idx >> 7, e = idx & 127;
        int id = ids[b * Nn + r0 + r];
        xs[r][e] = emb[(size_t)id * 128 + e];
    }
    __syncthreads();

    const float* wp[3];
    float bias[3];
    float* op[3];
#pragma unroll
    for (int s = 0; s < 3; s++) {
        int c = tid + 256 * s;
        if (c < 384) {
            wp[s] = fW + c; bias[s] = fb[c];
            op[s] = g_Wg + ((size_t)b * Nn + r0) * 384 + c;
        } else {
            int c2 = c - 384;
            wp[s] = rW + c2; bias[s] = rb[c2];
            op[s] = g_Wg + ((size_t)(Bb + b) * Nn + r0) * 384 + c2;
        }
    }

    float acc[8][3];
#pragma unroll
    for (int r = 0; r < 8; r++)
#pragma unroll
        for (int s = 0; s < 3; s++) acc[r][s] = 0.f;

    for (int e = 0; e < 128; e++) {
        float w0 = wp[0][(size_t)e * 384];
        float w1 = wp[1][(size_t)e * 384];
        float w2 = wp[2][(size_t)e * 384];
#pragma unroll
        for (int r = 0; r < 8; r++) {
            float x = xs[r][e];
            acc[r][0] = fmaf(x, w0, acc[r][0]);
            acc[r][1] = fmaf(x, w1, acc[r][1]);
            acc[r][2] = fmaf(x, w2, acc[r][2]);
        }
    }

#pragma unroll
    for (int r = 0; r < 8; r++)
#pragma unroll
        for (int s = 0; s < 3; s++)
            op[s][(size_t)r * 384] = acc[r][s] + bias[s];
}

// ---------------------------------------------------------------------------
// Lattice LSTM recurrence. One CTA per (dir,batch). 512 threads.
// KEY CHANGES vs R2:
//  - h/c history is an 8-slot ring buffer (word begin is always within the
//    last 5 steps since word_len < 6) -> smem drops 132KB -> 8KB.
//  - Wch split 64 rows in registers / 64 rows in smem -> no register spills
//    (R2 had 88 reg rows under a 128-reg cap -> spilled to L2 because smem
//    carveout left ~6KB of L1D).
//  - Invalid timesteps (uniform per CTA) skip all compute.
// ---------------------------------------------------------------------------
#define RREG 64
#define RSM  64

// smem float offsets
#define OFF_W   0                     // 64*512 = 32768
#define OFF_H   32768                 // 8*128 = 1024
#define OFF_C   33792                 // 1024
#define OFF_G   34816                 // 512
#define OFF_WT  35328                 // 384
#define OFF_CW  35712                 // 128
#define OFF_SE  35840                 // 128
#define OFF_SC  35968                 // 128
#define OFF_PS  36096                 // 512
#define FLT_END 36608
// ints: w_beg[64], w_end[64], wl_start[129], wl_idx[64], cur[128]
#define INT_CNT 449
#define SMEM_LAT (FLT_END * 4 + INT_CNT * 4)

__global__ void __launch_bounds__(512, 1) lattice_kernel(
    const float* __restrict__ Wch_f, const float* __restrict__ Wch_r,
    const int* __restrict__ word_begin, const int* __restrict__ word_len,
    const int* __restrict__ seqlen)
{
    extern __shared__ float sm[];
    float* wsm      = sm + OFF_W;
    float* h_ring   = sm + OFF_H;
    float* c_ring   = sm + OFF_C;
    float* gates    = sm + OFF_G;
    float* wtmp     = sm + OFF_WT;
    float* cw       = sm + OFF_CW;
    float* sum_ew   = sm + OFF_SE;
    float* sum_ewcw = sm + OFF_SC;
    float* psum     = sm + OFF_PS;
    int* ip        = (int*)(sm + FLT_END);
    int* w_beg     = ip;
    int* w_end     = ip + 64;
    int* wl_start  = ip + 128;     // 129 entries
    int* wl_idx    = ip + 257;     // 64
    int* cur       = ip + 321;     // 128

    int dirb = blockIdx.x;
    int dir  = dirb / Bb;
    int b    = dirb - dir * Bb;
    int tid  = threadIdx.x;
    int sl   = seqlen[b];

    const float* Wch  = dir ? Wch_r : Wch_f;
    const float* WwhT = g_WwhT + (size_t)dir * 384 * 128;
    const float* WlcT = g_WlcT + (size_t)dir * 128 * 128;
    const float* Xg_b = g_Xg + (size_t)dirb * Ss * 512;
    const float* Xl_b = g_Xl + (size_t)dirb * Ss * 128;
    const float* Wg_b = g_Wg + (size_t)dirb * Nn * 384;

    // Wch rows 0..63 -> registers (column tid); rows 64..127 -> smem
    float wreg[RREG];
#pragma unroll
    for (int r = 0; r < RREG; r++) wreg[r] = Wch[(size_t)r * 512 + tid];
#pragma unroll
    for (int r = 0; r < RSM; r++) wsm[r * 512 + tid] = Wch[(size_t)(RREG + r) * 512 + tid];

    if (tid < Hh) { h_ring[tid] = 0.f; c_ring[tid] = 0.f; }   // state 0 -> slot 0

    // per-word begin/end in this direction's coordinates
    if (tid < Nn) {
        int bg = word_begin[b * Nn + tid];
        int ln = word_len[b * Nn + tid];
        int ef = min(bg + ln, Ss - 1);
        bool valid = ef < sl;
        if (dir == 0) {
            w_beg[tid] = bg;
            w_end[tid] = valid ? ef : -1;
        } else {
            w_beg[tid] = Ss - 1 - ef;
            w_end[tid] = valid ? (Ss - 1 - bg) : -1;
        }
    }
    __syncthreads();

    // per-step word lists (counting sort), once
    if (tid == 0) {
        for (int t = 0; t < Ss; t++) cur[t] = 0;
        for (int n = 0; n < Nn; n++) { int e = w_end[n]; if (e >= 0) cur[e]++; }
        wl_start[0] = 0;
        for (int t = 0; t < Ss; t++) wl_start[t + 1] = wl_start[t] + cur[t];
        for (int t = 0; t < Ss; t++) cur[t] = wl_start[t];
        for (int n = 0; n < Nn; n++) { int e = w_end[n]; if (e >= 0) wl_idx[cur[e]++] = n; }
    }
    __syncthreads();

    for (int t = 0; t < Ss; t++) {
        int curS = (t & 7) * Hh;
        int nxtS = ((t + 1) & 7) * Hh;
        bool valid = (dir == 0) ? (t < sl) : (t >= Ss - sl);

        if (!valid) {
            // frozen step: copy state forward, emit zeros
            if (tid < Hh) {
                h_ring[nxtS + tid] = h_ring[curS + tid];
                c_ring[nxtS + tid] = c_ring[curS + tid];
                int tt = (dir == 0) ? t : (Ss - 1 - t);
                g_feats[((size_t)b * Ss + tt) * (2 * Hh) + dir * Hh + tid] = 0.f;
            }
            __syncthreads();
            continue;
        }

        int wls = wl_start[t];
        int m = wl_start[t + 1] - wls;

        // ---- char gates matvec ----
        {
            const float4* h4 = (const float4*)(h_ring + curS);
            float a0 = Xg_b[(size_t)t * 512 + tid];
            float a1 = 0.f;
#pragma unroll
            for (int q = 0; q < 16; q += 2) {
                float4 hv0 = h4[q], hv1 = h4[q + 1];
                a0 = fmaf(hv0.x, wreg[4 * q + 0], a0);
                a0 = fmaf(hv0.y, wreg[4 * q + 1], a0);
                a0 = fmaf(hv0.z, wreg[4 * q + 2], a0);
                a0 = fmaf(hv0.w, wreg[4 * q + 3], a0);
                a1 = fmaf(hv1.x, wreg[4 * q + 4], a1);
                a1 = fmaf(hv1.y, wreg[4 * q + 5], a1);
                a1 = fmaf(hv1.z, wreg[4 * q + 6], a1);
                a1 = fmaf(hv1.w, wreg[4 * q + 7], a1);
            }
#pragma unroll
            for (int q = 0; q < 16; q += 2) {
                float4 hv0 = h4[16 + q], hv1 = h4[17 + q];
                a0 = fmaf(hv0.x, wsm[(4 * q + 0) * 512 + tid], a0);
                a0 = fmaf(hv0.y, wsm[(4 * q + 1) * 512 + tid], a0);
                a0 = fmaf(hv0.z, wsm[(4 * q + 2) * 512 + tid], a0);
                a0 = fmaf(hv0.w, wsm[(4 * q + 3) * 512 + tid], a0);
                a1 = fmaf(hv1.x, wsm[(4 * q + 4) * 512 + tid], a1);
                a1 = fmaf(hv1.y, wsm[(4 * q + 5) * 512 + tid], a1);
                a1 = fmaf(hv1.z, wsm[(4 * q + 6) * 512 + tid], a1);
                a1 = fmaf(hv1.w, wsm[(4 * q + 7) * 512 + tid], a1);
            }
            gates[tid] = a0 + a1;
            if (m > 0 && tid < Hh) { sum_ew[tid] = 0.f; sum_ewcw[tid] = 0.f; }
        }
        __syncthreads();

        // ---- word lattice contributions ----
        for (int wv = 0; wv < m; wv++) {
            int n  = wl_idx[wls + wv];
            int bgS = (w_beg[n] & 7) * Hh;
            if (tid < 384) {
                const float4* hb4 = (const float4*)(h_ring + bgS);
                const float4* wT  = (const float4*)(WwhT + (size_t)tid * 128);
                float a0 = Wg_b[(size_t)n * 384 + tid], a1 = 0.f;
#pragma unroll
                for (int r = 0; r < 32; r += 2) {
                    float4 hv0 = hb4[r],     wv0 = wT[r];
                    float4 hv1 = hb4[r + 1], wv1 = wT[r + 1];
                    a0 = fmaf(hv0.x, wv0.x, a0);
                    a0 = fmaf(hv0.y, wv0.y, a0);
                    a0 = fmaf(hv0.z, wv0.z, a0);
                    a0 = fmaf(hv0.w, wv0.w, a0);
                    a1 = fmaf(hv1.x, wv1.x, a1);
                    a1 = fmaf(hv1.y, wv1.y, a1);
                    a1 = fmaf(hv1.z, wv1.z, a1);
                    a1 = fmaf(hv1.w, wv1.w, a1);
                }
                wtmp[tid] = a0 + a1;
            }
            __syncthreads();
            if (tid < Hh) {
                float wig = sigf(wtmp[tid]);
                float wfg = sigf(wtmp[Hh + tid]);
                float wgg = tanhf(wtmp[2 * Hh + tid]);
                cw[tid] = wfg * c_ring[bgS + tid] + wig * wgg;
            }
            __syncthreads();
            // Wlc matvec split-K over 4 slices
            {
                int col = tid & 127, sl4 = tid >> 7;
                const float4* c4 = (const float4*)cw + sl4 * 8;
                const float4* wT = (const float4*)(WlcT + (size_t)col * 128) + sl4 * 8;
                float p0 = 0.f, p1 = 0.f;
#pragma unroll
                for (int r = 0; r < 8; r += 2) {
                    float4 cv0 = c4[r],     wv0 = wT[r];
                    float4 cv1 = c4[r + 1], wv1 = wT[r + 1];
                    p0 = fmaf(cv0.x, wv0.x, p0);
                    p0 = fmaf(cv0.y, wv0.y, p0);
                    p0 = fmaf(cv0.z, wv0.z, p0);
                    p0 = fmaf(cv0.w, wv0.w, p0);
                    p1 = fmaf(cv1.x, wv1.x, p1);
                    p1 = fmaf(cv1.y, wv1.y, p1);
                    p1 = fmaf(cv1.z, wv1.z, p1);
                    p1 = fmaf(cv1.w, wv1.w, p1);
                }
                psum[sl4 * 128 + col] = p0 + p1;
            }
            __syncthreads();
            if (tid < Hh) {
                float a = Xl_b[(size_t)t * 128 + tid]
                        + psum[tid] + psum[128 + tid] + psum[256 + tid] + psum[384 + tid];
                float ew = expf(sigf(a));
                sum_ew[tid]   += ew;
                sum_ewcw[tid] += ew * cw[tid];
            }
            __syncthreads();
        }

        // ---- cell/state update ----
        if (tid < Hh) {
            float ig = sigf(gates[tid]);
            float fg = sigf(gates[Hh + tid]);
            float og = sigf(gates[2 * Hh + tid]);
            float gg = tanhf(gates[3 * Hh + tid]);
            float cp  = c_ring[curS + tid];
            float ct;
            if (m > 0) {
                float ec = expf(ig);
                ct = (ec * gg + sum_ewcw[tid]) / (ec + sum_ew[tid]);
            } else {
                ct = fg * cp + ig * gg;
            }
            float ht = og * tanhf(ct);
            h_ring[nxtS + tid] = ht;
            c_ring[nxtS + tid] = ct;
            int tt = (dir == 0) ? t : (Ss - 1 - t);
            g_feats[((size_t)b * Ss + tt) * (2 * Hh) + dir * Hh + tid] = ht;
        }
        __syncthreads();
    }
}

// ---------------------------------------------------------------------------
// Dense projection
// ---------------------------------------------------------------------------
__global__ void dense_kernel(const float* __restrict__ W, const float* __restrict__ bias)
{
    __shared__ float fs[8][2 * Hh];
    int row0 = blockIdx.x * 8;
    int tid = threadIdx.x;
    for (int idx = tid; idx < 8 * 2 * Hh; idx += 256) {
        int r = idx >> 8;
        int e = idx & 255;
        fs[r][e] = g_feats[(size_t)(row0 + r) * (2 * Hh) + e];
    }
    __syncthreads();
    int r = tid >> 5;
    int col = tid & 31;
    float acc = bias[col];
#pragma unroll 8
    for (int e = 0; e < 2 * Hh; e++) acc = fmaf(fs[r][e], W[e * Ll + col], acc);
    g_logits[(size_t)(row0 + r) * Ll + col] = acc;
}

// ---------------------------------------------------------------------------
// CRF
// ---------------------------------------------------------------------------
__global__ void crf_kernel(const int* __restrict__ label,
                           const int* __restrict__ seqlen,
                           const float* __restrict__ T)
{
    int b = blockIdx.x;
    int j = threadIdx.x;
    int sl = seqlen[b];
    const float* lg = g_logits + (size_t)b * Ss * Ll;
    const int*   lab = label + b * Ss;

    float Tc[32];
#pragma unroll
    for (int i = 0; i < 32; i++) Tc[i] = T[i * Ll + j];

    float gold = 0.f;
    for (int t = j; t < Ss; t += 32)
        if (t < sl) gold += lg[t * Ll + lab[t]];
    for (int t = j + 1; t < Ss; t += 32)
        if (t < sl) gold += T[lab[t - 1] * Ll + lab[t]];
#pragma unroll
    for (int o = 16; o; o >>= 1) gold += __shfl_xor_sync(0xffffffffu, gold, o);

    float alpha = lg[j];
    for (int t = 1; t < Ss; t++) {
        float vmax = -1e30f;
#pragma unroll
        for (int i = 0; i < 32; i++) {
            float ai = __shfl_sync(0xffffffffu, alpha, i);
            vmax = fmaxf(vmax, ai + Tc[i]);
        }
        float s = 0.f;
#pragma unroll
        for (int i = 0; i < 32; i++) {
            float ai = __shfl_sync(0xffffffffu, alpha, i);
            s += expf(ai + Tc[i] - vmax);
        }
        float na = vmax + logf(s) + lg[(size_t)t * Ll + j];
        if (t < sl) alpha = na;
    }
    float m2 = alpha;
#pragma unroll
    for (int o = 16; o; o >>= 1) m2 = fmaxf(m2, __shfl_xor_sync(0xffffffffu, m2, o));
    float s2 = expf(alpha - m2);
#pragma unroll
    for (int o = 16; o; o >>= 1) s2 += __shfl_xor_sync(0xffffffffu, s2, o);
    if (j == 0) g_pb[b] = (m2 + logf(s2)) - gold;
}

__global__ void finalize_kernel(float* __restrict__ out)
{
    float s = 0.f;
#pragma unroll
    for (int i = 0; i < Bb; i++) s += g_pb[i];
    out[0] = s / (float)Bb;
}

// ---------------------------------------------------------------------------
// Launch
// ---------------------------------------------------------------------------
extern "C" void kernel_launch(void* const* d_in, const int* in_sizes, int n_in,
                              void* d_out, int out_size)
{
    const int* char_ids = (const int*)d_in[0];
    const int* kb_ids   = (const int*)d_in[1];
    const int* wbeg     = (const int*)d_in[2];
    const int* wlen     = (const int*)d_in[3];
    const int* label    = (const int*)d_in[4];
    const int* slen     = (const int*)d_in[5];
    const float* char_emb = (const float*)d_in[6];
    const float* kb_emb   = (const float*)d_in[7];
    const float* dense_W  = (const float*)d_in[8];
    const float* dense_b  = (const float*)d_in[9];
    const float* crf_T    = (const float*)d_in[10];

    const float* f_Wcx = (const float*)d_in[11];
    const float* f_Wch = (const float*)d_in[12];
    const float* f_bc  = (const float*)d_in[13];
    const float* f_Wwx = (const float*)d_in[14];
    const float* f_Wwh = (const float*)d_in[15];
    const float* f_bw  = (const float*)d_in[16];
    const float* f_Wlx = (const float*)d_in[17];
    const float* f_Wlc = (const float*)d_in[18];
    const float* f_bl  = (const float*)d_in[19];

    const float* r_Wcx = (const float*)d_in[20];
    const float* r_Wch = (const float*)d_in[21];
    const float* r_bc  = (const float*)d_in[22];
    const float* r_Wwx = (const float*)d_in[23];
    const float* r_Wwh = (const float*)d_in[24];
    const float* r_bw  = (const float*)d_in[25];
    const float* r_Wlx = (const float*)d_in[26];
    const float* r_Wlc = (const float*)d_in[27];
    const float* r_bl  = (const float*)d_in[28];

    prep_transpose_kernel<<<dim3(192, 4), 256>>>(f_Wwh, r_Wwh, f_Wlc, r_Wlc);

    char_gather_kernel<<<dim3(Bb, Ss / 8), 256>>>(char_emb, char_ids,
        f_Wcx, r_Wcx, f_Wlx, r_Wlx, f_bc, r_bc, f_bl, r_bl);
    kb_gather_kernel<<<dim3(Bb, Nn / 8), 256>>>(kb_emb, kb_ids,
        f_Wwx, r_Wwx, f_bw, r_bw);

    cudaFuncSetAttribute(lattice_kernel, cudaFuncAttributeMaxDynamicSharedMemorySize, SMEM_LAT);
    lattice_kernel<<<2 * Bb, 512, SMEM_LAT>>>(f_Wch, r_Wch, wbeg, wlen, slen);

    dense_kernel<<<(Bb * Ss) / 8, 256>>>(dense_W, dense_b);
    crf_kernel<<<Bb, 32>>>(label, slen, crf_T);
    finalize_kernel<<<1, 1>>>((float*)d_out);
}